// round 6
// baseline (speedup 1.0000x reference)
#include <cuda_runtime.h>
#include <cuda_fp16.h>

#define RES 512
#define NC  32
#define TBL (RES * NC)
#define Q4  (NC / 4)            // uint4 slots per row

// Paired tables: entry (axis, r, c) = half2( v[c][r], v[c][r+1] - v[c][r] ).
// One 128B row read per axis gives value + delta for all 32 comps.
__device__ uint4 g_pair4[3 * RES * Q4];

// ---------------------------------------------------------------------------
__global__ void __launch_bounds__(256) pack_tables(
    const float* __restrict__ vx,
    const float* __restrict__ vy,
    const float* __restrict__ vz)
{
    int g = blockIdx.x * blockDim.x + threadIdx.x;
    if (g >= 3 * TBL) return;
    int a   = g / TBL;
    int rem = g - a * TBL;
    int r   = rem >> 5;
    int c   = rem & 31;
    const float* src = (a == 0) ? vx : (a == 1) ? vy : vz;
    float v0 = src[c * RES + r];
    float v1 = (r < RES - 1) ? src[c * RES + r + 1] : 0.0f;
    // store (v0, delta); delta at r=511 is never used (w == 0 there)
    reinterpret_cast<__half2*>(g_pair4)[g] = __floats2half2_rn(v0, v1 - v0);
}

// ---------------------------------------------------------------------------
struct PosPair { float x0, y0, z0, x1, y1, z1; };

__device__ __forceinline__ PosPair load_pos(const float* __restrict__ pos,
                                            int n, int npts)
{
    PosPair p;
    int a = min(n, npts - 1);
    int b = min(n + 4, npts - 1);
    const float* pa = pos + (size_t)a * 3;
    const float* pb = pos + (size_t)b * 3;
    p.x0 = __ldcs(pa + 0); p.y0 = __ldcs(pa + 1); p.z0 = __ldcs(pa + 2);
    p.x1 = __ldcs(pb + 0); p.y1 = __ldcs(pb + 1); p.z1 = __ldcs(pb + 2);
    return p;
}

// u in [-1,1] -> ix in [0,511]; (int)ix == floor, always in range.
__device__ __forceinline__ void prep1(float u, int q, int& off, float& w)
{
    float ix = fmaf(u, 255.5f, 255.5f);
    int   i0 = (int)ix;
    w   = ix - (float)i0;
    off = i0 * Q4 + q;
}

// p.{x,y,z,w} are half2 (v0, delta): f = fma(w, delta, v0)
__device__ __forceinline__ float4 lerp_pair(uint4 p, float w)
{
    float2 a = __half22float2(*reinterpret_cast<__half2*>(&p.x));
    float2 b = __half22float2(*reinterpret_cast<__half2*>(&p.y));
    float2 c = __half22float2(*reinterpret_cast<__half2*>(&p.z));
    float2 d = __half22float2(*reinterpret_cast<__half2*>(&p.w));
    float4 r;
    r.x = fmaf(w, a.y, a.x);
    r.y = fmaf(w, b.y, b.x);
    r.z = fmaf(w, c.y, c.x);
    r.w = fmaf(w, d.y, d.x);
    return r;
}

// Prep + issue the 6 table loads for one iteration (fills tn, wn).
__device__ __forceinline__ void stage_load(
    const PosPair& pp, int q,
    const uint4* __restrict__ bx, const uint4* __restrict__ by,
    const uint4* __restrict__ bz,
    uint4 (&tn)[6], float (&wn)[6])
{
    int o0, o1, o2, o3, o4, o5;
    prep1(pp.x0, q, o0, wn[0]);
    prep1(pp.y0, q, o1, wn[1]);
    prep1(pp.z0, q, o2, wn[2]);
    prep1(pp.x1, q, o3, wn[3]);
    prep1(pp.y1, q, o4, wn[4]);
    prep1(pp.z1, q, o5, wn[5]);
    tn[0] = bx[o0]; tn[1] = by[o1]; tn[2] = bz[o2];
    tn[3] = bx[o3]; tn[4] = by[o4]; tn[5] = bz[o5];
}

// Consume one iteration's table data: interpolate, product, store.
__device__ __forceinline__ void stage_compute(
    const uint4 (&tc)[6], const float (&wc)[6],
    float* __restrict__ out, int n, int npts, int q)
{
    float4 fx0 = lerp_pair(tc[0], wc[0]);
    float4 fy0 = lerp_pair(tc[1], wc[1]);
    float4 fz0 = lerp_pair(tc[2], wc[2]);
    float4 fx1 = lerp_pair(tc[3], wc[3]);
    float4 fy1 = lerp_pair(tc[4], wc[4]);
    float4 fz1 = lerp_pair(tc[5], wc[5]);

    float4 r0, r1;
    r0.x = fx0.x * fy0.x * fz0.x;
    r0.y = fx0.y * fy0.y * fz0.y;
    r0.z = fx0.z * fy0.z * fz0.z;
    r0.w = fx0.w * fy0.w * fz0.w;
    r1.x = fx1.x * fy1.x * fz1.x;
    r1.y = fx1.y * fy1.y * fz1.y;
    r1.z = fx1.z * fy1.z * fz1.z;
    r1.w = fx1.w * fy1.w * fz1.w;

    if (n < npts)
        __stcs(reinterpret_cast<float4*>(out + (size_t)n * NC + (q << 2)), r0);
    if (n + 4 < npts)
        __stcs(reinterpret_cast<float4*>(out + (size_t)(n + 4) * NC + (q << 2)), r1);
}

// ---------------------------------------------------------------------------
// Persistent, software-pipelined kernel.
// Warp = 8 points per iteration; thread handles points n, n+4.
// Table loads for iter i+1 issue before iter i's compute (ping-pong stages).
// Positions are prefetched two iterations ahead.
// ---------------------------------------------------------------------------
__global__ void __launch_bounds__(128, 5) cp_encode(
    const float* __restrict__ pos,
    float* __restrict__ out,
    int npts, int stride)
{
    int warp = (blockIdx.x * blockDim.x + threadIdx.x) >> 5;
    int lane = threadIdx.x & 31;
    int q    = lane & 7;
    int nw   = warp * 8;
    if (nw >= npts) return;

    int iters = (npts - nw + stride - 1) / stride;   // uniform per warp
    int n     = nw + (lane >> 3);

    const uint4* bx = g_pair4;
    const uint4* by = g_pair4 + RES * Q4;
    const uint4* bz = g_pair4 + 2 * RES * Q4;

    uint4 tA[6], tB[6];
    float wA[6], wB[6];

    // prologue: stage A = iter 0, pos for iter 1 prefetched
    PosPair ppA = load_pos(pos, n, npts);
    stage_load(ppA, q, bx, by, bz, tA, wA);
    PosPair ppB = load_pos(pos, n + stride, npts);

    int i = 0;
    while (true) {
        // ---- even phase: compute A, prefetch B ----
        if (i + 1 < iters) stage_load(ppB, q, bx, by, bz, tB, wB);
        if (i + 2 < iters) ppA = load_pos(pos, n + 2 * stride, npts);
        stage_compute(tA, wA, out, n, npts, q);
        n += stride;
        if (++i >= iters) break;

        // ---- odd phase: compute B, prefetch A ----
        if (i + 1 < iters) stage_load(ppA, q, bx, by, bz, tA, wA);
        if (i + 2 < iters) ppB = load_pos(pos, n + 2 * stride, npts);
        stage_compute(tB, wB, out, n, npts, q);
        n += stride;
        if (++i >= iters) break;
    }
}

// ---------------------------------------------------------------------------
extern "C" void kernel_launch(void* const* d_in, const int* in_sizes, int n_in,
                              void* d_out, int out_size)
{
    const float* positions = (const float*)d_in[0];
    const float* vec_x     = (const float*)d_in[1];
    const float* vec_y     = (const float*)d_in[2];
    const float* vec_z     = (const float*)d_in[3];
    float* out = (float*)d_out;

    int npts = in_sizes[0] / 3;

    int telems = 3 * TBL;
    pack_tables<<<(telems + 255) / 256, 256>>>(vec_x, vec_y, vec_z);

    // persistent grid: 5 blocks/SM * 148 SMs, 4 warps each; 8 pts per warp-iter
    const int blocks  = 148 * 5;
    const int threads = 128;
    int warps  = blocks * (threads / 32);
    int stride = warps * 8;

    cp_encode<<<blocks, threads>>>(positions, out, npts, stride);
}

// round 7
// speedup vs baseline: 1.0618x; 1.0618x over previous
#include <cuda_runtime.h>
#include <cuda_fp16.h>

#define RES 512
#define NC  32
#define TBL (RES * NC)
#define Q4  (NC / 4)            // uint4 slots per table row

// Paired tables: entry (axis, r, c) = half2( v[c][r], v[c][r+1] ).
// One 128B row read per axis delivers both interpolation neighbors for all
// 32 components. 3 axes * 512 rows * 8 uint4, +1 pad row so row i0+1 access
// at i0 == 511 (where w == 0 exactly) stays in bounds without a clamp.
__device__ uint4 g_pair4[3 * RES * Q4 + Q4];

// ---------------------------------------------------------------------------
// Prelude: transpose + pair-pack [C,R] fp32 -> [R,C] half2(v_r, v_{r+1}).
// ---------------------------------------------------------------------------
__global__ void __launch_bounds__(256) pack_tables(
    const float* __restrict__ vx,
    const float* __restrict__ vy,
    const float* __restrict__ vz)
{
    int g = blockIdx.x * blockDim.x + threadIdx.x;
    if (g >= 3 * TBL + NC) return;
    if (g >= 3 * TBL) {                       // pad row: value irrelevant (w==0), keep finite
        reinterpret_cast<__half2*>(g_pair4)[g] = __floats2half2_rn(0.f, 0.f);
        return;
    }
    int a   = g / TBL;
    int rem = g - a * TBL;
    int r   = rem >> 5;
    int c   = rem & 31;
    const float* src = (a == 0) ? vx : (a == 1) ? vy : vz;
    float v0 = src[c * RES + r];
    float v1 = (r < RES - 1) ? src[c * RES + r + 1] : 0.0f;
    reinterpret_cast<__half2*>(g_pair4)[g] = __floats2half2_rn(v0, v1);
}

// ---------------------------------------------------------------------------
// u in [-1,1] -> ix = u*255.5 + 255.5 in [0, 511]; (int) == floor, in range.
// ---------------------------------------------------------------------------
__device__ __forceinline__ void prep1(float u, int q, int& off, float& w)
{
    float ix = fmaf(u, 255.5f, 255.5f);
    int   i0 = (int)ix;
    w   = ix - (float)i0;
    off = i0 * Q4 + q;
}

// p.{x,y,z,w} are half2 (v0, v1): f = v0 + w*(v1 - v0)
__device__ __forceinline__ float4 lerp_pair(uint4 p, float w)
{
    float2 a = __half22float2(*reinterpret_cast<__half2*>(&p.x));
    float2 b = __half22float2(*reinterpret_cast<__half2*>(&p.y));
    float2 c = __half22float2(*reinterpret_cast<__half2*>(&p.z));
    float2 d = __half22float2(*reinterpret_cast<__half2*>(&p.w));
    float4 r;
    r.x = fmaf(w, a.y - a.x, a.x);
    r.y = fmaf(w, b.y - b.x, b.x);
    r.z = fmaf(w, c.y - c.x, c.x);
    r.w = fmaf(w, d.y - d.x, d.x);
    return r;
}

// ---------------------------------------------------------------------------
// Main kernel: warp = 8 points; thread handles points n0 and n0+4.
// lane l -> point offset (l>>3), uint4 slot (l&7) = 4 components.
// 6 independent LDG.128 table loads per thread, batched for MLP.
// 128-thread blocks + min-12-blocks bound -> ~94% theoretical occupancy.
// ---------------------------------------------------------------------------
__global__ void __launch_bounds__(128, 12) cp_encode(
    const float* __restrict__ pos,
    float* __restrict__ out,
    int npts)
{
    int warp = (blockIdx.x * blockDim.x + threadIdx.x) >> 5;
    int lane = threadIdx.x & 31;
    int n0   = warp * 8 + (lane >> 3);
    int n1   = n0 + 4;
    int q    = lane & 7;

    if (n0 >= npts) return;
    bool has1 = (n1 < npts);

    const float* p0 = pos + (size_t)n0 * 3;
    float x0 = __ldcs(p0 + 0);
    float y0 = __ldcs(p0 + 1);
    float z0 = __ldcs(p0 + 2);

    const float* p1 = pos + (size_t)(has1 ? n1 : n0) * 3;
    float x1 = __ldcs(p1 + 0);
    float y1 = __ldcs(p1 + 1);
    float z1 = __ldcs(p1 + 2);

    const uint4* bx = g_pair4;
    const uint4* by = g_pair4 + RES * Q4;
    const uint4* bz = g_pair4 + 2 * RES * Q4;

    int ox0, oy0, oz0, ox1, oy1, oz1;
    float wx0, wy0, wz0, wx1, wy1, wz1;
    prep1(x0, q, ox0, wx0);
    prep1(y0, q, oy0, wy0);
    prep1(z0, q, oz0, wz0);
    prep1(x1, q, ox1, wx1);
    prep1(y1, q, oy1, wy1);
    prep1(z1, q, oz1, wz1);

    // ---- batch all 6 independent table loads ----
    uint4 hx0 = bx[ox0];
    uint4 hy0 = by[oy0];
    uint4 hz0 = bz[oz0];
    uint4 hx1 = bx[ox1];
    uint4 hy1 = by[oy1];
    uint4 hz1 = bz[oz1];

    // ---- interpolate (fp32) + product ----
    float4 fx0 = lerp_pair(hx0, wx0);
    float4 fy0 = lerp_pair(hy0, wy0);
    float4 fz0 = lerp_pair(hz0, wz0);
    float4 fx1 = lerp_pair(hx1, wx1);
    float4 fy1 = lerp_pair(hy1, wy1);
    float4 fz1 = lerp_pair(hz1, wz1);

    float4 r0, r1;
    r0.x = fx0.x * fy0.x * fz0.x;
    r0.y = fx0.y * fy0.y * fz0.y;
    r0.z = fx0.z * fy0.z * fz0.z;
    r0.w = fx0.w * fy0.w * fz0.w;
    r1.x = fx1.x * fy1.x * fz1.x;
    r1.y = fx1.y * fy1.y * fz1.y;
    r1.z = fx1.z * fy1.z * fz1.z;
    r1.w = fx1.w * fy1.w * fz1.w;

    __stcs(reinterpret_cast<float4*>(out + (size_t)n0 * NC + (q << 2)), r0);
    if (has1)
        __stcs(reinterpret_cast<float4*>(out + (size_t)n1 * NC + (q << 2)), r1);
}

// ---------------------------------------------------------------------------
extern "C" void kernel_launch(void* const* d_in, const int* in_sizes, int n_in,
                              void* d_out, int out_size)
{
    const float* positions = (const float*)d_in[0];
    const float* vec_x     = (const float*)d_in[1];
    const float* vec_y     = (const float*)d_in[2];
    const float* vec_z     = (const float*)d_in[3];
    float* out = (float*)d_out;

    int npts = in_sizes[0] / 3;

    int telems = 3 * TBL + NC;
    pack_tables<<<(telems + 255) / 256, 256>>>(vec_x, vec_y, vec_z);

    // 32 points per 128-thread block (8 per warp)
    int blocks = (npts + 31) / 32;
    cp_encode<<<blocks, 128>>>(positions, out, npts);
}

// round 9
// speedup vs baseline: 1.1678x; 1.0997x over previous
#include <cuda_runtime.h>
#include <cuda_fp16.h>
#include <cstdint>

#define RES 512
#define NC  32
#define Q4  (NC / 4)            // uint4 slots per table row
#define ROWS4 (RES * Q4)        // uint4 per axis

// Table entry (axis, r, q) is a uint4:
//   .x = half2(v0[4q],   v0[4q+1])     .y = half2(v0[4q+2], v0[4q+3])
//   .z = half2(d [4q],   d [4q+1])     .w = half2(d [4q+2], d [4q+3])
// where v0 = v[r], d = v[r+1] - v[r].  One LDG.128 per point-axis gives
// value + delta for 4 components; lerp = 2 HFMA2.
__device__ uint4 g_tab[3 * ROWS4 + Q4];   // +1 pad row (w==0 there)

__device__ __forceinline__ unsigned int h2_to_u32(__half2 h)
{
    return *reinterpret_cast<unsigned int*>(&h);
}

// ---------------------------------------------------------------------------
__global__ void __launch_bounds__(256) pack_tables(
    const float* __restrict__ vx,
    const float* __restrict__ vy,
    const float* __restrict__ vz)
{
    int g = blockIdx.x * blockDim.x + threadIdx.x;
    if (g >= 3 * ROWS4 + Q4) return;
    if (g >= 3 * ROWS4) { g_tab[g] = make_uint4(0, 0, 0, 0); return; }

    int a   = g / ROWS4;
    int rem = g - a * ROWS4;
    int r   = rem >> 3;          // row 0..511
    int q   = rem & 7;           // uint4 slot
    const float* src = (a == 0) ? vx : (a == 1) ? vy : vz;

    float v0[4], d[4];
#pragma unroll
    for (int i = 0; i < 4; i++) {
        int c = q * 4 + i;
        v0[i] = src[c * RES + r];
        float v1 = (r < RES - 1) ? src[c * RES + r + 1] : 0.0f;
        d[i] = v1 - v0[i];
    }
    uint4 u;
    u.x = h2_to_u32(__floats2half2_rn(v0[0], v0[1]));
    u.y = h2_to_u32(__floats2half2_rn(v0[2], v0[3]));
    u.z = h2_to_u32(__floats2half2_rn(d[0],  d[1]));
    u.w = h2_to_u32(__floats2half2_rn(d[2],  d[3]));
    g_tab[g] = u;
}

// ---------------------------------------------------------------------------
// u in [-1,1] -> ix = u*255.5 + 255.5 in [0,511]; (int) == floor, in range.
// Returns uint4 offset and the weight as a broadcast half2.
// ---------------------------------------------------------------------------
__device__ __forceinline__ void prep1(float u, int q, int& off, __half2& w2)
{
    float ix = fmaf(u, 255.5f, 255.5f);
    int   i0 = (int)ix;
    w2  = __float2half2_rn(ix - (float)i0);
    off = i0 * Q4 + q;
}

// lerp 4 comps: f = v0 + w*d via 2 HFMA2, results as 2 half2.
__device__ __forceinline__ void lerp_h2(uint4 p, __half2 w2,
                                        __half2& f01, __half2& f23)
{
    f01 = __hfma2(w2, *reinterpret_cast<__half2*>(&p.z),
                       *reinterpret_cast<__half2*>(&p.x));
    f23 = __hfma2(w2, *reinterpret_cast<__half2*>(&p.w),
                       *reinterpret_cast<__half2*>(&p.y));
}

// fp32 triple product of 4 comps from half2 factors; writes float4.
__device__ __forceinline__ float4 prod3(__half2 x01, __half2 x23,
                                        __half2 y01, __half2 y23,
                                        __half2 z01, __half2 z23)
{
    float2 X01 = __half22float2(x01), X23 = __half22float2(x23);
    float2 Y01 = __half22float2(y01), Y23 = __half22float2(y23);
    float2 Z01 = __half22float2(z01), Z23 = __half22float2(z23);
    float4 r;
    r.x = X01.x * Y01.x * Z01.x;
    r.y = X01.y * Y01.y * Z01.y;
    r.z = X23.x * Y23.x * Z23.x;
    r.w = X23.y * Y23.y * Z23.y;
    return r;
}

// ---------------------------------------------------------------------------
// Main kernel: warp = 8 points; thread handles points n0 and n0+4.
// lane l -> point offset (l>>3), uint4 slot (l&7) = 4 components.
// 6 independent LDG.128 table loads; lerp entirely in HFMA2.
// ---------------------------------------------------------------------------
__global__ void __launch_bounds__(128, 12) cp_encode(
    const float* __restrict__ pos,
    float* __restrict__ out,
    int npts)
{
    int warp = (blockIdx.x * blockDim.x + threadIdx.x) >> 5;
    int lane = threadIdx.x & 31;
    int n0   = warp * 8 + (lane >> 3);
    int n1   = n0 + 4;
    int q    = lane & 7;

    if (n0 >= npts) return;
    bool has1 = (n1 < npts);

    const float* p0 = pos + (size_t)n0 * 3;
    float x0 = __ldcs(p0 + 0);
    float y0 = __ldcs(p0 + 1);
    float z0 = __ldcs(p0 + 2);

    const float* p1 = pos + (size_t)(has1 ? n1 : n0) * 3;
    float x1 = __ldcs(p1 + 0);
    float y1 = __ldcs(p1 + 1);
    float z1 = __ldcs(p1 + 2);

    const uint4* bx = g_tab;
    const uint4* by = g_tab + ROWS4;
    const uint4* bz = g_tab + 2 * ROWS4;

    int ox0, oy0, oz0, ox1, oy1, oz1;
    __half2 wx0, wy0, wz0, wx1, wy1, wz1;
    prep1(x0, q, ox0, wx0);
    prep1(y0, q, oy0, wy0);
    prep1(z0, q, oz0, wz0);
    prep1(x1, q, ox1, wx1);
    prep1(y1, q, oy1, wy1);
    prep1(z1, q, oz1, wz1);

    // ---- batch all 6 independent table loads ----
    uint4 hx0 = bx[ox0];
    uint4 hy0 = by[oy0];
    uint4 hz0 = bz[oz0];
    uint4 hx1 = bx[ox1];
    uint4 hy1 = by[oy1];
    uint4 hz1 = bz[oz1];

    // ---- lerp (HFMA2) ----
    __half2 fx0a, fx0b, fy0a, fy0b, fz0a, fz0b;
    __half2 fx1a, fx1b, fy1a, fy1b, fz1a, fz1b;
    lerp_h2(hx0, wx0, fx0a, fx0b);
    lerp_h2(hy0, wy0, fy0a, fy0b);
    lerp_h2(hz0, wz0, fz0a, fz0b);
    lerp_h2(hx1, wx1, fx1a, fx1b);
    lerp_h2(hy1, wy1, fy1a, fy1b);
    lerp_h2(hz1, wz1, fz1a, fz1b);

    // ---- fp32 triple product + store ----
    float4 r0 = prod3(fx0a, fx0b, fy0a, fy0b, fz0a, fz0b);
    float4 r1 = prod3(fx1a, fx1b, fy1a, fy1b, fz1a, fz1b);

    __stcs(reinterpret_cast<float4*>(out + (size_t)n0 * NC + (q << 2)), r0);
    if (has1)
        __stcs(reinterpret_cast<float4*>(out + (size_t)n1 * NC + (q << 2)), r1);
}

// ---------------------------------------------------------------------------
extern "C" void kernel_launch(void* const* d_in, const int* in_sizes, int n_in,
                              void* d_out, int out_size)
{
    const float* positions = (const float*)d_in[0];
    const float* vec_x     = (const float*)d_in[1];
    const float* vec_y     = (const float*)d_in[2];
    const float* vec_z     = (const float*)d_in[3];
    float* out = (float*)d_out;

    int npts = in_sizes[0] / 3;

    int telems = 3 * ROWS4 + Q4;
    pack_tables<<<(telems + 255) / 256, 256>>>(vec_x, vec_y, vec_z);

    int blocks = (npts + 31) / 32;   // 32 points per 128-thread block
    cp_encode<<<blocks, 128>>>(positions, out, npts);
}

// round 10
// speedup vs baseline: 1.2048x; 1.0317x over previous
#include <cuda_runtime.h>
#include <cuda_fp16.h>
#include <cstdint>

#define RES 512
#define NC  32
#define Q4  (NC / 4)            // uint4 slots per table row
#define ROWS4 (RES * Q4)        // uint4 per axis
#define TAB4  (3 * ROWS4)       // total uint4 in packed tables (192KB)

// Packed table entry (axis, r, q) as uint4:
//   .x = half2(v0[4q],   v0[4q+1])   .y = half2(v0[4q+2], v0[4q+3])
//   .z = half2(d [4q],   d [4q+1])   .w = half2(d [4q+2], d [4q+3])
// v0 = v[r], d = v[r+1] - v[r]. One 16B read per (point, axis, 4comps);
// lerp = 2 HFMA2.
__device__ uint4 g_tab[TAB4];

__device__ __forceinline__ unsigned int h2_to_u32(__half2 h)
{
    return *reinterpret_cast<unsigned int*>(&h);
}

// ---------------------------------------------------------------------------
__global__ void __launch_bounds__(256) pack_tables(
    const float* __restrict__ vx,
    const float* __restrict__ vy,
    const float* __restrict__ vz)
{
    int g = blockIdx.x * blockDim.x + threadIdx.x;
    if (g >= TAB4) return;

    int a   = g / ROWS4;
    int rem = g - a * ROWS4;
    int r   = rem >> 3;          // row 0..511
    int q   = rem & 7;           // uint4 slot
    const float* src = (a == 0) ? vx : (a == 1) ? vy : vz;

    float v0[4], d[4];
#pragma unroll
    for (int i = 0; i < 4; i++) {
        int c = q * 4 + i;
        v0[i] = src[c * RES + r];
        float v1 = (r < RES - 1) ? src[c * RES + r + 1] : 0.0f;
        d[i] = v1 - v0[i];
    }
    uint4 u;
    u.x = h2_to_u32(__floats2half2_rn(v0[0], v0[1]));
    u.y = h2_to_u32(__floats2half2_rn(v0[2], v0[3]));
    u.z = h2_to_u32(__floats2half2_rn(d[0],  d[1]));
    u.w = h2_to_u32(__floats2half2_rn(d[2],  d[3]));
    g_tab[g] = u;
}

// ---------------------------------------------------------------------------
// u in [-1,1] -> ix = u*255.5 + 255.5 in [0,511]; (int) == floor, in range.
// ---------------------------------------------------------------------------
__device__ __forceinline__ void prep1(float u, int q, int& off, __half2& w2)
{
    float ix = fmaf(u, 255.5f, 255.5f);
    int   i0 = (int)ix;
    w2  = __float2half2_rn(ix - (float)i0);
    off = i0 * Q4 + q;
}

__device__ __forceinline__ void lerp_h2(uint4 p, __half2 w2,
                                        __half2& f01, __half2& f23)
{
    f01 = __hfma2(w2, *reinterpret_cast<__half2*>(&p.z),
                       *reinterpret_cast<__half2*>(&p.x));
    f23 = __hfma2(w2, *reinterpret_cast<__half2*>(&p.w),
                       *reinterpret_cast<__half2*>(&p.y));
}

__device__ __forceinline__ float4 prod3(__half2 x01, __half2 x23,
                                        __half2 y01, __half2 y23,
                                        __half2 z01, __half2 z23)
{
    float2 X01 = __half22float2(x01), X23 = __half22float2(x23);
    float2 Y01 = __half22float2(y01), Y23 = __half22float2(y23);
    float2 Z01 = __half22float2(z01), Z23 = __half22float2(z23);
    float4 r;
    r.x = X01.x * Y01.x * Z01.x;
    r.y = X01.y * Y01.y * Z01.y;
    r.z = X23.x * Y23.x * Z23.x;
    r.w = X23.y * Y23.y * Z23.y;
    return r;
}

// ---------------------------------------------------------------------------
// Persistent kernel, tables in SMEM (192KB dynamic).
// Block = 1024 threads (32 warps); each block copies g_tab -> smem once,
// then grid-strides over points. Warp = 8 points/iter; thread handles
// points n, n+4; lane l -> point offset (l>>3), uint4 slot (l&7).
// Table reads are LDS.128 (smem crossbar), freeing l1tex for stores+pos.
// ---------------------------------------------------------------------------
__global__ void __launch_bounds__(1024, 1) cp_encode(
    const float* __restrict__ pos,
    float* __restrict__ out,
    int npts, int stride)
{
    extern __shared__ uint4 s_tab[];

    // cooperative table copy: 12288 uint4, 1024 threads -> 12 LDG.128 each
#pragma unroll
    for (int i = threadIdx.x; i < TAB4; i += 1024)
        s_tab[i] = g_tab[i];
    __syncthreads();

    int warp = (blockIdx.x * blockDim.x + threadIdx.x) >> 5;
    int lane = threadIdx.x & 31;
    int q    = lane & 7;

    const uint4* bx = s_tab;
    const uint4* by = s_tab + ROWS4;
    const uint4* bz = s_tab + 2 * ROWS4;

    for (int n0 = warp * 8 + (lane >> 3); n0 < npts; n0 += stride) {
        int  n1   = n0 + 4;
        bool has1 = (n1 < npts);

        const float* p0 = pos + (size_t)n0 * 3;
        float x0 = __ldcs(p0 + 0);
        float y0 = __ldcs(p0 + 1);
        float z0 = __ldcs(p0 + 2);

        const float* p1 = pos + (size_t)(has1 ? n1 : n0) * 3;
        float x1 = __ldcs(p1 + 0);
        float y1 = __ldcs(p1 + 1);
        float z1 = __ldcs(p1 + 2);

        int ox0, oy0, oz0, ox1, oy1, oz1;
        __half2 wx0, wy0, wz0, wx1, wy1, wz1;
        prep1(x0, q, ox0, wx0);
        prep1(y0, q, oy0, wy0);
        prep1(z0, q, oz0, wz0);
        prep1(x1, q, ox1, wx1);
        prep1(y1, q, oy1, wy1);
        prep1(z1, q, oz1, wz1);

        // ---- 6 independent LDS.128 table reads ----
        uint4 hx0 = bx[ox0];
        uint4 hy0 = by[oy0];
        uint4 hz0 = bz[oz0];
        uint4 hx1 = bx[ox1];
        uint4 hy1 = by[oy1];
        uint4 hz1 = bz[oz1];

        // ---- lerp (HFMA2) ----
        __half2 fx0a, fx0b, fy0a, fy0b, fz0a, fz0b;
        __half2 fx1a, fx1b, fy1a, fy1b, fz1a, fz1b;
        lerp_h2(hx0, wx0, fx0a, fx0b);
        lerp_h2(hy0, wy0, fy0a, fy0b);
        lerp_h2(hz0, wz0, fz0a, fz0b);
        lerp_h2(hx1, wx1, fx1a, fx1b);
        lerp_h2(hy1, wy1, fy1a, fy1b);
        lerp_h2(hz1, wz1, fz1a, fz1b);

        // ---- fp32 triple product + store ----
        float4 r0 = prod3(fx0a, fx0b, fy0a, fy0b, fz0a, fz0b);
        float4 r1 = prod3(fx1a, fx1b, fy1a, fy1b, fz1a, fz1b);

        __stcs(reinterpret_cast<float4*>(out + (size_t)n0 * NC + (q << 2)), r0);
        if (has1)
            __stcs(reinterpret_cast<float4*>(out + (size_t)n1 * NC + (q << 2)), r1);
    }
}

// ---------------------------------------------------------------------------
extern "C" void kernel_launch(void* const* d_in, const int* in_sizes, int n_in,
                              void* d_out, int out_size)
{
    const float* positions = (const float*)d_in[0];
    const float* vec_x     = (const float*)d_in[1];
    const float* vec_y     = (const float*)d_in[2];
    const float* vec_z     = (const float*)d_in[3];
    float* out = (float*)d_out;

    int npts = in_sizes[0] / 3;

    pack_tables<<<(TAB4 + 255) / 256, 256>>>(vec_x, vec_y, vec_z);

    const int smem_bytes = TAB4 * sizeof(uint4);   // 196608
    static bool attr_set = false;
    if (!attr_set) {
        cudaFuncSetAttribute(cp_encode,
                             cudaFuncAttributeMaxDynamicSharedMemorySize,
                             smem_bytes);
        attr_set = true;
    }

    const int blocks  = 148;          // persistent: 1 block/SM (192KB smem)
    const int threads = 1024;         // 32 warps
    int warps  = blocks * (threads / 32);
    int stride = warps * 8;           // points per full-grid sweep

    cp_encode<<<blocks, threads, smem_bytes>>>(positions, out, npts, stride);
}